// round 15
// baseline (speedup 1.0000x reference)
#include <cuda_runtime.h>
#include <cuda_fp16.h>
#include <math.h>
#include <stdint.h>

// ---------------------------------------------------------------------------
// Problem constants
// ---------------------------------------------------------------------------
#define BATCH   64
#define B2      32
#define NTOK    257
#define C       768
#define HID     3072
#define NH      12
#define HD      64
#define T       (BATCH * NTOK)      // 16448 tokens total
#define TH      (B2 * NTOK)         // 8224 tokens per half

// ---------------------------------------------------------------------------
// Scratch (static device allocations; no cudaMalloc allowed)
// ---------------------------------------------------------------------------
__device__ __half g_normed_h[T * C];
__device__ __half g_qkv_h[T * 3 * C];
__device__ __half g_attn_h[T * C];
__device__ float  g_x1[T * C];
__device__ float  g_beff[C];
__device__ __half g_hL_h[TH * HID];
__device__ float  g_pre2[TH * HID];
__device__ float  g_pre3[TH * HID];
__device__ __half g_h1h[TH * HID];
__device__ __half g_h2h[TH * HID];
__device__ __half g_h3h[TH * HID];
__device__ float  g_P2[TH * 384];      // FC2 small partials (alpha folded)
__device__ float  g_P3[TH * 256];
// transposed fp16 weights: WT[n][k], k contiguous
__device__ __half g_wqkvT[3 * C * C];
__device__ __half g_wprojT[C * C];
__device__ __half g_weffT[C * C];
__device__ __half g_wfc1T[HID * C];
__device__ __half g_wfc2T[C * HID];

// ---------------------------------------------------------------------------
// Helpers
// ---------------------------------------------------------------------------
__device__ __forceinline__ float gelu_exact(float v) {
    return 0.5f * v * (1.0f + erff(v * 0.70710678118654752f));
}
__device__ __forceinline__ uint32_t smem_u32(const void* p) {
    uint32_t a;
    asm("{ .reg .u64 t; cvta.to.shared.u64 t, %1; cvt.u32.u64 %0, t; }"
        : "=r"(a) : "l"(p));
    return a;
}
__device__ __forceinline__ void cp_async16(uint32_t dst, const void* src, int srcbytes) {
    asm volatile("cp.async.cg.shared.global [%0], [%1], 16, %2;"
                 :: "r"(dst), "l"(src), "r"(srcbytes));
}
#define CP_COMMIT() asm volatile("cp.async.commit_group;" ::: "memory")
#define CP_WAIT2()  asm volatile("cp.async.wait_group 2;" ::: "memory")

__device__ __forceinline__ void mma_f16(float* c, const uint32_t* a, const uint32_t* b) {
    asm volatile(
        "mma.sync.aligned.m16n8k16.row.col.f32.f16.f16.f32 "
        "{%0,%1,%2,%3}, {%4,%5,%6,%7}, {%8,%9}, {%0,%1,%2,%3};"
        : "+f"(c[0]), "+f"(c[1]), "+f"(c[2]), "+f"(c[3])
        : "r"(a[0]), "r"(a[1]), "r"(a[2]), "r"(a[3]), "r"(b[0]), "r"(b[1]));
}
__device__ __forceinline__ void ldsm_x4(uint32_t* r, uint32_t addr) {
    asm volatile("ldmatrix.sync.aligned.m8n8.x4.shared.b16 {%0,%1,%2,%3}, [%4];"
        : "=r"(r[0]), "=r"(r[1]), "=r"(r[2]), "=r"(r[3]) : "r"(addr));
}
__device__ __forceinline__ void ldsm_x2(uint32_t* r, uint32_t addr) {
    asm volatile("ldmatrix.sync.aligned.m8n8.x2.shared.b16 {%0,%1}, [%2];"
        : "=r"(r[0]), "=r"(r[1]) : "r"(addr));
}
__device__ __forceinline__ __half2 u32_as_h2(uint32_t w) {
    return *reinterpret_cast<__half2*>(&w);
}

extern __shared__ char dsmem[];

// GEMM smem: A/B tiles 128 rows x 32 halves, pitch 40 halves (80B), 5 stages
#define APITCH_H 40
#define A_BYTES  (128 * APITCH_H * 2)   // 10240
#define STG_B    (2 * A_BYTES)          // 20480
#define STAGES   5
#define GEMM_SMEM (STAGES * STG_B)      // 102400

// ---------------------------------------------------------------------------
// Multi-task fp16 GEMM: flattened grid; each CTA resolves its task from the
// batch table (by-value kernel arg), then computes a 128x128 tile.
// Pipeline: prefetch distance 3, wait_group 2 per chunk (RAW on chunk i),
// __syncthreads every SECOND chunk (WAR: iter i writes stage (i+3)%5, last
// read at iter i-2; the sync at i or i-1 proves all warps are past it).
// ---------------------------------------------------------------------------
struct GemmTask {
    const __half* A; const __half* B;
    void* Cc; const float* Cin;
    const float* bias; const float* resid;
    const float* alpha_ptr; __half* gback;
    int lda, ldb, ldc, out_half, ldcin, ldr;
    int M, K, aidx, do_gelu, bnCnt, ctaStart;
};
struct GemmBatch { GemmTask t[4]; int n; };

__global__ void __launch_bounds__(256, 2) hgemm_multi(GemmBatch nb)
{
    const int bid = blockIdx.x;
    int ti = 0;
    #pragma unroll
    for (int j = 1; j < 4; j++)
        if (j < nb.n && bid >= nb.t[j].ctaStart) ti = j;
    const GemmTask& tk = nb.t[ti];
    const int local = bid - tk.ctaStart;
    const int bn = local % tk.bnCnt;
    const int bm = local / tk.bnCnt;

    const int tid = threadIdx.x;
    const int wid = tid >> 5, lid = tid & 31;
    const int warpM = wid >> 2;          // 0..1  (64 rows)
    const int warpN = wid & 3;           // 0..3  (32 cols)
    const int lq = lid >> 2;             // 0..7
    const int lr = lid & 3;              // 0..3

    const uint32_t sbase = smem_u32(dsmem);
    const int ldRow = tid >> 2;          // 0..63 (+64)
    const int ldQ   = tid & 3;

    // ldmatrix lane address components
    const int aRowSel = (lid & 7) + ((lid >> 3) & 1) * 8;
    const int aKb16   = ((lid >> 4) & 1) * 16;
    const int bRowSel = lid & 7;
    const int bKb16   = ((lid >> 3) & 1) * 16;

    float acc[4][4][4];
    #pragma unroll
    for (int mi = 0; mi < 4; mi++)
        #pragma unroll
        for (int ni = 0; ni < 4; ni++)
            #pragma unroll
            for (int j = 0; j < 4; j++) acc[mi][ni][j] = 0.f;

    const __half* A = tk.A; const __half* B = tk.B;
    const int lda = tk.lda, ldb = tk.ldb, M = tk.M;
    const int nch = tk.K >> 5;

    auto issue = [&](int ci, int st) {
        int k0 = ci << 5;
        uint32_t aB = sbase + (uint32_t)st * STG_B;
        uint32_t bB = aB + A_BYTES;
        #pragma unroll
        for (int u = 0; u < 2; u++) {
            int row = ldRow + u * 64;
            int r = bm * 128 + row;
            bool ok = (r < M);
            const __half* src = A + (size_t)(ok ? r : 0) * lda + k0 + ldQ * 8;
            cp_async16(aB + (uint32_t)(row * 80 + ldQ * 16), src, ok ? 16 : 0);
        }
        #pragma unroll
        for (int u = 0; u < 2; u++) {
            int row = ldRow + u * 64;
            const __half* src = B + (size_t)(bn * 128 + row) * ldb + k0 + ldQ * 8;
            cp_async16(bB + (uint32_t)(row * 80 + ldQ * 16), src, 16);
        }
    };

    // prologue: 3 chunks (all call sites have nch >= 4)
    #pragma unroll
    for (int s = 0; s < 3; s++) {
        if (s < nch) issue(s, s);
        CP_COMMIT();
    }

    for (int i = 0; i < nch; i++) {
        CP_WAIT2();                       // chunk i resident
        if ((i & 1) == 0) __syncthreads(); // WAR fence every 2 chunks
        int nx = i + 3;
        if (nx < nch) issue(nx, nx % STAGES);
        CP_COMMIT();

        int st = i % STAGES;
        uint32_t aStage = sbase + (uint32_t)st * STG_B;
        uint32_t bStage = aStage + A_BYTES;

        #pragma unroll
        for (int ks = 0; ks < 2; ks++) {
            uint32_t afr[4][4], bfr[4][2];
            #pragma unroll
            for (int mi = 0; mi < 4; mi++) {
                int row = warpM * 64 + mi * 16 + aRowSel;
                ldsm_x4(afr[mi], aStage + (uint32_t)(row * 80 + ks * 32 + aKb16));
            }
            #pragma unroll
            for (int ni = 0; ni < 4; ni++) {
                int row = warpN * 32 + ni * 8 + bRowSel;
                ldsm_x2(bfr[ni], bStage + (uint32_t)(row * 80 + ks * 32 + bKb16));
            }
            #pragma unroll
            for (int mi = 0; mi < 4; mi++)
                #pragma unroll
                for (int ni = 0; ni < 4; ni++)
                    mma_f16(acc[mi][ni], afr[mi], bfr[ni]);
        }
    }

    // ---- epilogue ----
    float alpha = tk.alpha_ptr ? tk.alpha_ptr[tk.aidx] : 1.0f;
    #pragma unroll
    for (int mi = 0; mi < 4; mi++) {
        #pragma unroll
        for (int h = 0; h < 2; h++) {
            int r = bm * 128 + warpM * 64 + mi * 16 + lq + h * 8;
            if (r >= M) continue;
            #pragma unroll
            for (int ni = 0; ni < 4; ni++) {
                int cc = bn * 128 + warpN * 32 + ni * 8 + lr * 2;
                float v0 = acc[mi][ni][h * 2 + 0];
                float v1 = acc[mi][ni][h * 2 + 1];
                if (tk.bias) { v0 += tk.bias[cc]; v1 += tk.bias[cc + 1]; }
                v0 *= alpha; v1 *= alpha;
                if (tk.Cin) {
                    const float* cp = tk.Cin + (size_t)r * tk.ldcin + cc;
                    float c0 = cp[0], c1 = cp[1];
                    v0 += c0; v1 += c1;
                    if (tk.gback) {
                        __half2* gp = (__half2*)(tk.gback + (size_t)r * tk.ldcin + cc);
                        *gp = __floats2half2_rn(gelu_exact(c0), gelu_exact(c1));
                    }
                }
                if (tk.resid) {
                    const float* rp = tk.resid + (size_t)r * tk.ldr + cc;
                    v0 += rp[0]; v1 += rp[1];
                }
                if (tk.do_gelu) { v0 = gelu_exact(v0); v1 = gelu_exact(v1); }
                if (tk.out_half) {
                    __half2* op = (__half2*)((__half*)tk.Cc + (size_t)r * tk.ldc + cc);
                    *op = __floats2half2_rn(v0, v1);
                } else {
                    float2* op = (float2*)((float*)tk.Cc + (size_t)r * tk.ldc + cc);
                    *op = make_float2(v0, v1);
                }
            }
        }
    }
}

// ---------------------------------------------------------------------------
// FC2-small merge: outS[:, :384] += P2; outS[:, :256] += P3 (alphas folded)
// ---------------------------------------------------------------------------
__global__ void merge_kernel(float* __restrict__ outS,
                             const float* __restrict__ P2,
                             const float* __restrict__ P3)
{
    int i = blockIdx.x * blockDim.x + threadIdx.x;   // over TH*96 float4s
    if (i >= TH * 96) return;
    int r = i / 96, c4 = i % 96;
    float4 v = *(float4*)(outS + (size_t)r * C + c4 * 4);
    float4 p2 = *(const float4*)(P2 + (size_t)r * 384 + c4 * 4);
    v.x += p2.x; v.y += p2.y; v.z += p2.z; v.w += p2.w;
    if (c4 < 64) {
        float4 p3 = *(const float4*)(P3 + (size_t)r * 256 + c4 * 4);
        v.x += p3.x; v.y += p3.y; v.z += p3.z; v.w += p3.w;
    }
    *(float4*)(outS + (size_t)r * C + c4 * 4) = v;
}

// ---------------------------------------------------------------------------
// LayerNorm: fp32 in, half out
// ---------------------------------------------------------------------------
__global__ __launch_bounds__(256) void ln_kernel(
    const float* __restrict__ x,
    const float* __restrict__ gl, const float* __restrict__ bl,
    const float* __restrict__ gs, const float* __restrict__ bs,
    __half* __restrict__ out)
{
    int row = blockIdx.x;
    const float* xr = x + (size_t)row * C;
    int t = threadIdx.x;
    float v0 = xr[t], v1 = xr[t + 256], v2 = xr[t + 512];
    float s = v0 + v1 + v2;
    float ss = v0 * v0 + v1 * v1 + v2 * v2;
    #pragma unroll
    for (int o = 16; o; o >>= 1) {
        s  += __shfl_xor_sync(0xffffffffu, s, o);
        ss += __shfl_xor_sync(0xffffffffu, ss, o);
    }
    __shared__ float sm[2][8];
    int warp = t >> 5, lane = t & 31;
    if (!lane) { sm[0][warp] = s; sm[1][warp] = ss; }
    __syncthreads();
    if (t < 32) {
        float a = (lane < 8) ? sm[0][lane] : 0.f;
        float b = (lane < 8) ? sm[1][lane] : 0.f;
        #pragma unroll
        for (int o = 4; o; o >>= 1) {
            a += __shfl_xor_sync(0xffffffffu, a, o);
            b += __shfl_xor_sync(0xffffffffu, b, o);
        }
        if (!lane) { sm[0][0] = a; sm[1][0] = b; }
    }
    __syncthreads();
    float mean = sm[0][0] * (1.0f / C);
    float var  = sm[1][0] * (1.0f / C) - mean * mean;
    float rstd = rsqrtf(var + 1e-5f);
    const float* g  = (row < TH) ? gl : gs;
    const float* bb = (row < TH) ? bl : bs;
    __half* orow = out + (size_t)row * C;
    orow[t]       = __float2half_rn((v0 - mean) * rstd * g[t]       + bb[t]);
    orow[t + 256] = __float2half_rn((v1 - mean) * rstd * g[t + 256] + bb[t + 256]);
    orow[t + 512] = __float2half_rn((v2 - mean) * rstd * g[t + 512] + bb[t + 512]);
}

// ---------------------------------------------------------------------------
// Fused weight prep: all 5 transposes (fp32 [K][N] -> half [N][K]) + beff,
// one flattened grid.  Block ranges hardcoded:
//   [0,1728)     w_qkv  -> g_wqkvT   (N=2304, K=768,  nbX=72)
//   [1728,2304)  w_proj -> g_wprojT  (N=768,  K=768,  nbX=24)
//   [2304,2880)  w_proj -> g_weffT   (masked, nbX=24)
//   [2880,5184)  w_fc1  -> g_wfc1T   (N=3072, K=768,  nbX=96)
//   [5184,7488)  w_fc2  -> g_wfc2T   (N=768,  K=3072, nbX=24)
//   7488         beff
// ---------------------------------------------------------------------------
__global__ void prep_kernel(const float* __restrict__ w_qkv,
                            const float* __restrict__ w_proj,
                            const float* __restrict__ w_fc1,
                            const float* __restrict__ w_fc2,
                            const float* __restrict__ b_proj,
                            const float* __restrict__ g)
{
    int bidx = blockIdx.x;
    if (bidx == 7488) {
        int i = threadIdx.y * 32 + threadIdx.x;
        for (; i < C; i += 256) {
            float m = g[0];
            if (i < 384) m += g[1];
            if (i < 256) m += g[2];
            g_beff[i] = b_proj[i] * m;
        }
        return;
    }
    const float* in; __half* outp; int K, N, nbX, mode, rel;
    if (bidx < 1728)      { in = w_qkv;  outp = g_wqkvT;  K = C;   N = 3 * C; nbX = 72; mode = 0; rel = bidx; }
    else if (bidx < 2304) { in = w_proj; outp = g_wprojT; K = C;   N = C;     nbX = 24; mode = 0; rel = bidx - 1728; }
    else if (bidx < 2880) { in = w_proj; outp = g_weffT;  K = C;   N = C;     nbX = 24; mode = 1; rel = bidx - 2304; }
    else if (bidx < 5184) { in = w_fc1;  outp = g_wfc1T;  K = C;   N = HID;   nbX = 96; mode = 0; rel = bidx - 2880; }
    else                  { in = w_fc2;  outp = g_wfc2T;  K = HID; N = C;     nbX = 24; mode = 0; rel = bidx - 5184; }

    __shared__ float tile[32][33];
    int nb = (rel % nbX) * 32, kb = (rel / nbX) * 32;
    int tx = threadIdx.x, ty = threadIdx.y;   // 32 x 8
    #pragma unroll
    for (int j = 0; j < 32; j += 8)
        tile[ty + j][tx] = in[(size_t)(kb + ty + j) * N + nb + tx];
    __syncthreads();
    #pragma unroll
    for (int j = 0; j < 32; j += 8) {
        int n = nb + ty + j, k = kb + tx;
        float v = tile[tx][ty + j];
        if (mode) {
            float m = g[0];
            if (k < 384 && n < 384) m += g[1];
            if (k < 256 && n < 256) m += g[2];
            v *= m;
        }
        outp[(size_t)n * K + k] = __float2half_rn(v);
    }
}

// ---------------------------------------------------------------------------
// Attention: one block per (b, h). Half in/out, fp32 softmax.
// ---------------------------------------------------------------------------
#define KPITCH 33
#define PSTRIDE 258

__global__ __launch_bounds__(256) void attn_kernel(
    const __half* __restrict__ qkv, __half* __restrict__ out)
{
    int bh = blockIdx.x;
    int b = bh / NH, h = bh % NH;
    uint32_t* Kw = (uint32_t*)dsmem;
    uint32_t* Vp = Kw + NTOK * KPITCH;
    float*    Psh = (float*)(Vp + NTOK * KPITCH);
    uint32_t* Qw  = (uint32_t*)(Psh + 8 * PSTRIDE);

    int tid = threadIdx.x, warp = tid >> 5, lane = tid & 31;
    const __half* base = qkv + (size_t)b * NTOK * (3 * C) + h * HD;

    for (int idx = tid; idx < NTOK * 32; idx += 256) {
        int m = idx >> 5, w = idx & 31;
        const __half* row = base + (size_t)m * (3 * C);
        __half2 kh = *(const __half2*)(row + C + 2 * w);
        Kw[m * KPITCH + w] = *(uint32_t*)&kh;
        const __half* vr = row + 2 * C;
        __half2 vh = __halves2half2(vr[w], vr[w + 32]);
        Vp[m * KPITCH + w] = *(uint32_t*)&vh;
    }
    __syncthreads();

    float* myP = Psh + warp * PSTRIDE;
    uint32_t* myQ = Qw + warp * 32;

    for (int n = warp; n < NTOK; n += 8) {
        const __half* qrow = base + (size_t)n * (3 * C);
        __half2 qh = *(const __half2*)(qrow + 2 * lane);
        myQ[lane] = *(uint32_t*)&qh;
        __syncwarp();

        float lmax = -1e30f;
        for (int m = lane; m < NTOK; m += 32) {
            const uint32_t* kr = &Kw[m * KPITCH];
            float s0 = 0.f, s1 = 0.f;
            #pragma unroll
            for (int w = 0; w < 32; w += 2) {
                float2 q0 = __half22float2(u32_as_h2(myQ[w]));
                float2 k0 = __half22float2(u32_as_h2(kr[w]));
                float2 q1 = __half22float2(u32_as_h2(myQ[w + 1]));
                float2 k1 = __half22float2(u32_as_h2(kr[w + 1]));
                s0 += q0.x * k0.x + q0.y * k0.y;
                s1 += q1.x * k1.x + q1.y * k1.y;
            }
            float s = (s0 + s1) * 0.125f;
            myP[m] = s;
            lmax = fmaxf(lmax, s);
        }
        #pragma unroll
        for (int o = 16; o; o >>= 1)
            lmax = fmaxf(lmax, __shfl_xor_sync(0xffffffffu, lmax, o));

        float lsum = 0.f;
        for (int m = lane; m < NTOK; m += 32) {
            float p = expf(myP[m] - lmax);
            myP[m] = p;
            lsum += p;
        }
        #pragma unroll
        for (int o = 16; o; o >>= 1)
            lsum += __shfl_xor_sync(0xffffffffu, lsum, o);
        __syncwarp();

        float a0[4] = {0.f, 0.f, 0.f, 0.f};
        float a1[4] = {0.f, 0.f, 0.f, 0.f};
        int m = 0;
        for (; m + 4 <= NTOK; m += 4) {
            #pragma unroll
            for (int u = 0; u < 4; u++) {
                float p = myP[m + u];
                float2 vf = __half22float2(u32_as_h2(Vp[(m + u) * KPITCH + lane]));
                a0[u] += p * vf.x;
                a1[u] += p * vf.y;
            }
        }
        for (; m < NTOK; m++) {
            float p = myP[m];
            float2 vf = __half22float2(u32_as_h2(Vp[m * KPITCH + lane]));
            a0[0] += p * vf.x;
            a1[0] += p * vf.y;
        }
        float inv = 1.0f / lsum;
        float o0 = (a0[0] + a0[1] + a0[2] + a0[3]) * inv;
        float o1 = (a1[0] + a1[1] + a1[2] + a1[3]) * inv;

        __half* orow = out + ((size_t)b * NTOK + n) * C + h * HD;
        orow[lane]      = __float2half_rn(o0);
        orow[lane + 32] = __float2half_rn(o1);
        __syncwarp();
    }
}

// ---------------------------------------------------------------------------
// Launch
// ---------------------------------------------------------------------------
static inline void* symv(const void* symbol) {
    void* p = nullptr;
    cudaGetSymbolAddress(&p, symbol);
    return p;
}

static GemmTask mk_task(const __half* A, int lda, const __half* B, int ldb,
                        void* Cc, int ldc, int out_half,
                        const float* Cin, int ldcin,
                        const float* bias, const float* resid, int ldr,
                        int M, int K, int N,
                        const float* alpha_ptr, int aidx, int do_gelu,
                        __half* gback)
{
    GemmTask t;
    t.A = A; t.lda = lda; t.B = B; t.ldb = ldb;
    t.Cc = Cc; t.ldc = ldc; t.out_half = out_half;
    t.Cin = Cin; t.ldcin = ldcin; t.bias = bias;
    t.resid = resid; t.ldr = ldr;
    t.M = M; t.K = K;
    t.alpha_ptr = alpha_ptr; t.aidx = aidx; t.do_gelu = do_gelu;
    t.gback = gback;
    t.bnCnt = N / 128; t.ctaStart = 0;
    return t;
}

static void launch_batch(GemmTask* tasks, int n)
{
    GemmBatch nb;
    int total = 0;
    for (int i = 0; i < n; i++) {
        tasks[i].ctaStart = total;
        total += tasks[i].bnCnt * ((tasks[i].M + 127) / 128);
        nb.t[i] = tasks[i];
    }
    nb.n = n;
    for (int i = n; i < 4; i++) nb.t[i] = tasks[n - 1];
    hgemm_multi<<<total, 256, GEMM_SMEM>>>(nb);
}

extern "C" void kernel_launch(void* const* d_in, const int* in_sizes, int n_in,
                              void* d_out, int out_size)
{
    const float* x      = (const float*)d_in[0];
    const float* gw     = (const float*)d_in[1];
    const float* n1l_g  = (const float*)d_in[2];
    const float* n1l_b  = (const float*)d_in[3];
    const float* n1s_g  = (const float*)d_in[4];
    const float* n1s_b  = (const float*)d_in[5];
    const float* w_qkv  = (const float*)d_in[6];
    const float* w_proj = (const float*)d_in[7];
    const float* b_proj = (const float*)d_in[8];
    const float* n2l_g  = (const float*)d_in[9];
    const float* n2l_b  = (const float*)d_in[10];
    const float* n2s_g  = (const float*)d_in[11];
    const float* n2s_b  = (const float*)d_in[12];
    const float* w_fc1  = (const float*)d_in[13];
    const float* b_fc1  = (const float*)d_in[14];
    const float* w_fc2  = (const float*)d_in[15];
    const float* b_fc2  = (const float*)d_in[16];
    float* out = (float*)d_out;

    __half* normed = (__half*)symv(g_normed_h);
    __half* qkv    = (__half*)symv(g_qkv_h);
    __half* attn   = (__half*)symv(g_attn_h);
    float*  x1     = (float*)symv(g_x1);
    float*  beff   = (float*)symv(g_beff);
    __half* hL     = (__half*)symv(g_hL_h);
    float*  pre2   = (float*)symv(g_pre2);
    float*  pre3   = (float*)symv(g_pre3);
    __half* h1h    = (__half*)symv(g_h1h);
    __half* h2h    = (__half*)symv(g_h2h);
    __half* h3h    = (__half*)symv(g_h3h);
    float*  P2     = (float*)symv(g_P2);
    float*  P3     = (float*)symv(g_P3);
    __half* wqkvT  = (__half*)symv(g_wqkvT);
    __half* wprojT = (__half*)symv(g_wprojT);
    __half* weffT  = (__half*)symv(g_weffT);
    __half* wfc1T  = (__half*)symv(g_wfc1T);
    __half* wfc2T  = (__half*)symv(g_wfc2T);

    const int attn_smem = (2 * NTOK * KPITCH + 8 * PSTRIDE + 8 * 32) * 4;
    cudaFuncSetAttribute(attn_kernel, cudaFuncAttributeMaxDynamicSharedMemorySize,
                         attn_smem);
    cudaFuncSetAttribute(hgemm_multi, cudaFuncAttributeMaxDynamicSharedMemorySize,
                         GEMM_SMEM);

    // 0. fused weight prep (5 transposes + beff, one launch)
    prep_kernel<<<7489, dim3(32, 8)>>>(w_qkv, w_proj, w_fc1, w_fc2, b_proj, gw);

    // 1. LN1
    ln_kernel<<<T, 256>>>(x, n1l_g, n1l_b, n1s_g, n1s_b, normed);

    // 2. QKV
    {
        GemmTask t[1] = { mk_task(normed, C, wqkvT, C, qkv, 3 * C, 1,
                                  nullptr, 0, nullptr, nullptr, 0,
                                  T, C, 3 * C, nullptr, 0, 0, nullptr) };
        launch_batch(t, 1);
    }

    // 3. Attention
    attn_kernel<<<BATCH * NH, 256, attn_smem>>>(qkv, attn);

    // 4. Projection + residual (large + small concurrently)
    {
        GemmTask t[2] = {
            mk_task(attn, C, wprojT, C, x1, C, 0,
                    nullptr, 0, b_proj, x, C, TH, C, C, nullptr, 0, 0, nullptr),
            mk_task(attn + (size_t)TH * C, C, weffT, C,
                    x1 + (size_t)TH * C, C, 0,
                    nullptr, 0, beff, x + (size_t)TH * C, C, TH, C, C,
                    nullptr, 0, 0, nullptr) };
        launch_batch(t, 2);
    }

    // 5. LN2
    ln_kernel<<<T, 256>>>(x1, n2l_g, n2l_b, n2s_g, n2s_b, normed);

    // 6. FC1: large + pre3 concurrently, then dependent chain
    const __half* ns2 = normed + (size_t)TH * C;
    {
        GemmTask t[2] = {
            mk_task(normed, C, wfc1T, C, hL, HID, 1,
                    nullptr, 0, b_fc1, nullptr, 0, TH, C, HID,
                    nullptr, 0, 1, nullptr),
            mk_task(ns2, C, wfc1T, C, pre3, HID, 0,
                    nullptr, 0, b_fc1, nullptr, 0, TH, 256, HID,
                    nullptr, 0, 0, nullptr) };
        launch_batch(t, 2);
    }
    {
        GemmTask t[1] = { mk_task(ns2 + 256, C, wfc1T + 256, C, pre2, HID, 0,
                                  pre3, HID, nullptr, nullptr, 0, TH, 128, HID,
                                  nullptr, 0, 0, h3h) };
        launch_batch(t, 1);
    }
    {
        GemmTask t[1] = { mk_task(ns2 + 384, C, wfc1T + 384, C, h1h, HID, 1,
                                  pre2, HID, nullptr, nullptr, 0, TH, 384, HID,
                                  nullptr, 0, 1, h2h) };
        launch_batch(t, 1);
    }

    // 7. FC2: all four tasks concurrent; smalls 2/3 go to partial buffers
    float* outS = out + (size_t)TH * C;
    const float* x1S = x1 + (size_t)TH * C;
    {
        GemmTask t[4] = {
            mk_task(hL, HID, wfc2T, HID, out, C, 0,
                    nullptr, 0, b_fc2, x1, C, TH, HID, C, nullptr, 0, 0, nullptr),
            mk_task(h1h, HID, wfc2T, HID, outS, C, 0,
                    nullptr, 0, b_fc2, x1S, C, TH, HID, C, gw, 0, 0, nullptr),
            mk_task(h2h, HID, wfc2T, HID, P2, 384, 0,
                    nullptr, 0, b_fc2, nullptr, 0, TH, HID, 384, gw, 1, 0, nullptr),
            mk_task(h3h, HID, wfc2T, HID, P3, 256, 0,
                    nullptr, 0, b_fc2, nullptr, 0, TH, HID, 256, gw, 2, 0, nullptr) };
        launch_batch(t, 4);
    }
    merge_kernel<<<(TH * 96 + 255) / 256, 256>>>(outS, P2, P3);
}

// round 16
// speedup vs baseline: 1.5107x; 1.5107x over previous
#include <cuda_runtime.h>
#include <cuda_fp16.h>
#include <math.h>
#include <stdint.h>

// ---------------------------------------------------------------------------
// Problem constants
// ---------------------------------------------------------------------------
#define BATCH   64
#define B2      32
#define NTOK    257
#define C       768
#define HID     3072
#define NH      12
#define HD      64
#define T       (BATCH * NTOK)      // 16448 tokens total
#define TH      (B2 * NTOK)         // 8224 tokens per half

// ---------------------------------------------------------------------------
// Scratch (static device allocations; no cudaMalloc allowed)
// ---------------------------------------------------------------------------
__device__ __half g_normed_h[T * C];
__device__ __half g_qkv_h[T * 3 * C];
__device__ __half g_attn_h[T * C];
__device__ float  g_x1[T * C];
__device__ float  g_beff[C];
__device__ __half g_hL_h[TH * HID];
__device__ float  g_pre2[TH * HID];
__device__ float  g_pre3[TH * HID];
__device__ __half g_h1h[TH * HID];
__device__ __half g_h2h[TH * HID];
__device__ __half g_h3h[TH * HID];
__device__ float  g_P2[TH * 384];      // FC2 small partials (alpha folded)
__device__ float  g_P3[TH * 256];
// transposed fp16 weights: WT[n][k], k contiguous
__device__ __half g_wqkvT[3 * C * C];
__device__ __half g_wprojT[C * C];
__device__ __half g_weffT[C * C];
__device__ __half g_wfc1T[HID * C];
__device__ __half g_wfc2T[C * HID];

// ---------------------------------------------------------------------------
// Helpers
// ---------------------------------------------------------------------------
__device__ __forceinline__ float gelu_exact(float v) {
    return 0.5f * v * (1.0f + erff(v * 0.70710678118654752f));
}
__device__ __forceinline__ uint32_t smem_u32(const void* p) {
    uint32_t a;
    asm("{ .reg .u64 t; cvta.to.shared.u64 t, %1; cvt.u32.u64 %0, t; }"
        : "=r"(a) : "l"(p));
    return a;
}
__device__ __forceinline__ void cp_async16(uint32_t dst, const void* src, int srcbytes) {
    asm volatile("cp.async.cg.shared.global [%0], [%1], 16, %2;"
                 :: "r"(dst), "l"(src), "r"(srcbytes));
}
#define CP_COMMIT() asm volatile("cp.async.commit_group;" ::: "memory")
#define CP_WAIT3()  asm volatile("cp.async.wait_group 3;" ::: "memory")

__device__ __forceinline__ void mma_f16(float* c, const uint32_t* a, const uint32_t* b) {
    asm volatile(
        "mma.sync.aligned.m16n8k16.row.col.f32.f16.f16.f32 "
        "{%0,%1,%2,%3}, {%4,%5,%6,%7}, {%8,%9}, {%0,%1,%2,%3};"
        : "+f"(c[0]), "+f"(c[1]), "+f"(c[2]), "+f"(c[3])
        : "r"(a[0]), "r"(a[1]), "r"(a[2]), "r"(a[3]), "r"(b[0]), "r"(b[1]));
}
__device__ __forceinline__ void ldsm_x4(uint32_t* r, uint32_t addr) {
    asm volatile("ldmatrix.sync.aligned.m8n8.x4.shared.b16 {%0,%1,%2,%3}, [%4];"
        : "=r"(r[0]), "=r"(r[1]), "=r"(r[2]), "=r"(r[3]) : "r"(addr));
}
__device__ __forceinline__ void ldsm_x2(uint32_t* r, uint32_t addr) {
    asm volatile("ldmatrix.sync.aligned.m8n8.x2.shared.b16 {%0,%1}, [%2];"
        : "=r"(r[0]), "=r"(r[1]) : "r"(addr));
}
__device__ __forceinline__ __half2 u32_as_h2(uint32_t w) {
    return *reinterpret_cast<__half2*>(&w);
}

extern __shared__ char dsmem[];

// GEMM smem: A/B tiles 128 rows x 32 halves, pitch 40 halves (80B), 5 stages
#define APITCH_H 40
#define A_BYTES  (128 * APITCH_H * 2)   // 10240
#define STG_B    (2 * A_BYTES)          // 20480
#define STAGES   5
#define GEMM_SMEM (STAGES * STG_B)      // 102400

// ---------------------------------------------------------------------------
// Multi-task fp16 GEMM: flattened grid; each CTA resolves its task from the
// batch table (by-value kernel arg), then computes a 128x128 tile.
// Pipeline (R14-proven): prologue fills 4 stages, wait_group 3 + sync per chunk.
// ---------------------------------------------------------------------------
struct GemmTask {
    const __half* A; const __half* B;
    void* Cc; const float* Cin;
    const float* bias; const float* resid;
    const float* alpha_ptr; __half* gback;
    int lda, ldb, ldc, out_half, ldcin, ldr;
    int M, K, aidx, do_gelu, bnCnt, ctaStart;
};
struct GemmBatch { GemmTask t[4]; int n; };

__global__ void __launch_bounds__(256, 2) hgemm_multi(GemmBatch nb)
{
    const int bid = blockIdx.x;
    int ti = 0;
    #pragma unroll
    for (int j = 1; j < 4; j++)
        if (j < nb.n && bid >= nb.t[j].ctaStart) ti = j;
    const GemmTask& tk = nb.t[ti];
    const int local = bid - tk.ctaStart;
    const int bn = local % tk.bnCnt;
    const int bm = local / tk.bnCnt;

    const int tid = threadIdx.x;
    const int wid = tid >> 5, lid = tid & 31;
    const int warpM = wid >> 2;          // 0..1  (64 rows)
    const int warpN = wid & 3;           // 0..3  (32 cols)
    const int lq = lid >> 2;             // 0..7
    const int lr = lid & 3;              // 0..3

    const uint32_t sbase = smem_u32(dsmem);
    const int ldRow = tid >> 2;          // 0..63 (+64)
    const int ldQ   = tid & 3;

    // ldmatrix lane address components
    const int aRowSel = (lid & 7) + ((lid >> 3) & 1) * 8;
    const int aKb16   = ((lid >> 4) & 1) * 16;
    const int bRowSel = lid & 7;
    const int bKb16   = ((lid >> 3) & 1) * 16;

    float acc[4][4][4];
    #pragma unroll
    for (int mi = 0; mi < 4; mi++)
        #pragma unroll
        for (int ni = 0; ni < 4; ni++)
            #pragma unroll
            for (int j = 0; j < 4; j++) acc[mi][ni][j] = 0.f;

    const __half* A = tk.A; const __half* B = tk.B;
    const int lda = tk.lda, ldb = tk.ldb, M = tk.M;
    const int nch = tk.K >> 5;

    auto issue = [&](int ci, int st) {
        int k0 = ci << 5;
        uint32_t aB = sbase + (uint32_t)st * STG_B;
        uint32_t bB = aB + A_BYTES;
        #pragma unroll
        for (int u = 0; u < 2; u++) {
            int row = ldRow + u * 64;
            int r = bm * 128 + row;
            bool ok = (r < M);
            const __half* src = A + (size_t)(ok ? r : 0) * lda + k0 + ldQ * 8;
            cp_async16(aB + (uint32_t)(row * 80 + ldQ * 16), src, ok ? 16 : 0);
        }
        #pragma unroll
        for (int u = 0; u < 2; u++) {
            int row = ldRow + u * 64;
            const __half* src = B + (size_t)(bn * 128 + row) * ldb + k0 + ldQ * 8;
            cp_async16(bB + (uint32_t)(row * 80 + ldQ * 16), src, 16);
        }
    };

    // prologue: first STAGES-1 chunks (guarded; nch >= 4 at every call site)
    #pragma unroll
    for (int s = 0; s < STAGES - 1; s++) {
        if (s < nch) issue(s, s);
        CP_COMMIT();
    }

    for (int i = 0; i < nch; i++) {
        CP_WAIT3();
        __syncthreads();
        int nx = i + STAGES - 1;
        if (nx < nch) issue(nx, nx % STAGES);
        CP_COMMIT();

        int st = i % STAGES;
        uint32_t aStage = sbase + (uint32_t)st * STG_B;
        uint32_t bStage = aStage + A_BYTES;

        #pragma unroll
        for (int ks = 0; ks < 2; ks++) {
            uint32_t afr[4][4], bfr[4][2];
            #pragma unroll
            for (int mi = 0; mi < 4; mi++) {
                int row = warpM * 64 + mi * 16 + aRowSel;
                ldsm_x4(afr[mi], aStage + (uint32_t)(row * 80 + ks * 32 + aKb16));
            }
            #pragma unroll
            for (int ni = 0; ni < 4; ni++) {
                int row = warpN * 32 + ni * 8 + bRowSel;
                ldsm_x2(bfr[ni], bStage + (uint32_t)(row * 80 + ks * 32 + bKb16));
            }
            #pragma unroll
            for (int mi = 0; mi < 4; mi++)
                #pragma unroll
                for (int ni = 0; ni < 4; ni++)
                    mma_f16(acc[mi][ni], afr[mi], bfr[ni]);
        }
    }

    // ---- epilogue ----
    float alpha = tk.alpha_ptr ? tk.alpha_ptr[tk.aidx] : 1.0f;
    #pragma unroll
    for (int mi = 0; mi < 4; mi++) {
        #pragma unroll
        for (int h = 0; h < 2; h++) {
            int r = bm * 128 + warpM * 64 + mi * 16 + lq + h * 8;
            if (r >= M) continue;
            #pragma unroll
            for (int ni = 0; ni < 4; ni++) {
                int cc = bn * 128 + warpN * 32 + ni * 8 + lr * 2;
                float v0 = acc[mi][ni][h * 2 + 0];
                float v1 = acc[mi][ni][h * 2 + 1];
                if (tk.bias) { v0 += tk.bias[cc]; v1 += tk.bias[cc + 1]; }
                v0 *= alpha; v1 *= alpha;
                if (tk.Cin) {
                    const float* cp = tk.Cin + (size_t)r * tk.ldcin + cc;
                    float c0 = cp[0], c1 = cp[1];
                    v0 += c0; v1 += c1;
                    if (tk.gback) {
                        __half2* gp = (__half2*)(tk.gback + (size_t)r * tk.ldcin + cc);
                        *gp = __floats2half2_rn(gelu_exact(c0), gelu_exact(c1));
                    }
                }
                if (tk.resid) {
                    const float* rp = tk.resid + (size_t)r * tk.ldr + cc;
                    v0 += rp[0]; v1 += rp[1];
                }
                if (tk.do_gelu) { v0 = gelu_exact(v0); v1 = gelu_exact(v1); }
                if (tk.out_half) {
                    __half2* op = (__half2*)((__half*)tk.Cc + (size_t)r * tk.ldc + cc);
                    *op = __floats2half2_rn(v0, v1);
                } else {
                    float2* op = (float2*)((float*)tk.Cc + (size_t)r * tk.ldc + cc);
                    *op = make_float2(v0, v1);
                }
            }
        }
    }
}

// ---------------------------------------------------------------------------
// FC2-small merge: outS[:, :384] += P2; outS[:, :256] += P3 (alphas folded)
// ---------------------------------------------------------------------------
__global__ void merge_kernel(float* __restrict__ outS,
                             const float* __restrict__ P2,
                             const float* __restrict__ P3)
{
    int i = blockIdx.x * blockDim.x + threadIdx.x;   // over TH*96 float4s
    if (i >= TH * 96) return;
    int r = i / 96, c4 = i % 96;
    float4 v = *(float4*)(outS + (size_t)r * C + c4 * 4);
    float4 p2 = *(const float4*)(P2 + (size_t)r * 384 + c4 * 4);
    v.x += p2.x; v.y += p2.y; v.z += p2.z; v.w += p2.w;
    if (c4 < 64) {
        float4 p3 = *(const float4*)(P3 + (size_t)r * 256 + c4 * 4);
        v.x += p3.x; v.y += p3.y; v.z += p3.z; v.w += p3.w;
    }
    *(float4*)(outS + (size_t)r * C + c4 * 4) = v;
}

// ---------------------------------------------------------------------------
// LayerNorm: fp32 in, half out
// ---------------------------------------------------------------------------
__global__ __launch_bounds__(256) void ln_kernel(
    const float* __restrict__ x,
    const float* __restrict__ gl, const float* __restrict__ bl,
    const float* __restrict__ gs, const float* __restrict__ bs,
    __half* __restrict__ out)
{
    int row = blockIdx.x;
    const float* xr = x + (size_t)row * C;
    int t = threadIdx.x;
    float v0 = xr[t], v1 = xr[t + 256], v2 = xr[t + 512];
    float s = v0 + v1 + v2;
    float ss = v0 * v0 + v1 * v1 + v2 * v2;
    #pragma unroll
    for (int o = 16; o; o >>= 1) {
        s  += __shfl_xor_sync(0xffffffffu, s, o);
        ss += __shfl_xor_sync(0xffffffffu, ss, o);
    }
    __shared__ float sm[2][8];
    int warp = t >> 5, lane = t & 31;
    if (!lane) { sm[0][warp] = s; sm[1][warp] = ss; }
    __syncthreads();
    if (t < 32) {
        float a = (lane < 8) ? sm[0][lane] : 0.f;
        float b = (lane < 8) ? sm[1][lane] : 0.f;
        #pragma unroll
        for (int o = 4; o; o >>= 1) {
            a += __shfl_xor_sync(0xffffffffu, a, o);
            b += __shfl_xor_sync(0xffffffffu, b, o);
        }
        if (!lane) { sm[0][0] = a; sm[1][0] = b; }
    }
    __syncthreads();
    float mean = sm[0][0] * (1.0f / C);
    float var  = sm[1][0] * (1.0f / C) - mean * mean;
    float rstd = rsqrtf(var + 1e-5f);
    const float* g  = (row < TH) ? gl : gs;
    const float* bb = (row < TH) ? bl : bs;
    __half* orow = out + (size_t)row * C;
    orow[t]       = __float2half_rn((v0 - mean) * rstd * g[t]       + bb[t]);
    orow[t + 256] = __float2half_rn((v1 - mean) * rstd * g[t + 256] + bb[t + 256]);
    orow[t + 512] = __float2half_rn((v2 - mean) * rstd * g[t + 512] + bb[t + 512]);
}

// ---------------------------------------------------------------------------
// Fused weight prep: all 5 transposes (fp32 [K][N] -> half [N][K]) + beff,
// one flattened grid.  Block ranges hardcoded:
//   [0,1728)     w_qkv  -> g_wqkvT   (N=2304, K=768,  nbX=72)
//   [1728,2304)  w_proj -> g_wprojT  (N=768,  K=768,  nbX=24)
//   [2304,2880)  w_proj -> g_weffT   (masked, nbX=24)
//   [2880,5184)  w_fc1  -> g_wfc1T   (N=3072, K=768,  nbX=96)
//   [5184,7488)  w_fc2  -> g_wfc2T   (N=768,  K=3072, nbX=24)
//   7488         beff
// ---------------------------------------------------------------------------
__global__ void prep_kernel(const float* __restrict__ w_qkv,
                            const float* __restrict__ w_proj,
                            const float* __restrict__ w_fc1,
                            const float* __restrict__ w_fc2,
                            const float* __restrict__ b_proj,
                            const float* __restrict__ g)
{
    int bidx = blockIdx.x;
    if (bidx == 7488) {
        int i = threadIdx.y * 32 + threadIdx.x;
        for (; i < C; i += 256) {
            float m = g[0];
            if (i < 384) m += g[1];
            if (i < 256) m += g[2];
            g_beff[i] = b_proj[i] * m;
        }
        return;
    }
    const float* in; __half* outp; int K, N, nbX, mode, rel;
    if (bidx < 1728)      { in = w_qkv;  outp = g_wqkvT;  K = C;   N = 3 * C; nbX = 72; mode = 0; rel = bidx; }
    else if (bidx < 2304) { in = w_proj; outp = g_wprojT; K = C;   N = C;     nbX = 24; mode = 0; rel = bidx - 1728; }
    else if (bidx < 2880) { in = w_proj; outp = g_weffT;  K = C;   N = C;     nbX = 24; mode = 1; rel = bidx - 2304; }
    else if (bidx < 5184) { in = w_fc1;  outp = g_wfc1T;  K = C;   N = HID;   nbX = 96; mode = 0; rel = bidx - 2880; }
    else                  { in = w_fc2;  outp = g_wfc2T;  K = HID; N = C;     nbX = 24; mode = 0; rel = bidx - 5184; }

    __shared__ float tile[32][33];
    int nb = (rel % nbX) * 32, kb = (rel / nbX) * 32;
    int tx = threadIdx.x, ty = threadIdx.y;   // 32 x 8
    #pragma unroll
    for (int j = 0; j < 32; j += 8)
        tile[ty + j][tx] = in[(size_t)(kb + ty + j) * N + nb + tx];
    __syncthreads();
    #pragma unroll
    for (int j = 0; j < 32; j += 8) {
        int n = nb + ty + j, k = kb + tx;
        float v = tile[tx][ty + j];
        if (mode) {
            float m = g[0];
            if (k < 384 && n < 384) m += g[1];
            if (k < 256 && n < 256) m += g[2];
            v *= m;
        }
        outp[(size_t)n * K + k] = __float2half_rn(v);
    }
}

// ---------------------------------------------------------------------------
// Attention: one block per (b, h). Half in/out, fp32 softmax.
// ---------------------------------------------------------------------------
#define KPITCH 33
#define PSTRIDE 258

__global__ __launch_bounds__(256) void attn_kernel(
    const __half* __restrict__ qkv, __half* __restrict__ out)
{
    int bh = blockIdx.x;
    int b = bh / NH, h = bh % NH;
    uint32_t* Kw = (uint32_t*)dsmem;
    uint32_t* Vp = Kw + NTOK * KPITCH;
    float*    Psh = (float*)(Vp + NTOK * KPITCH);
    uint32_t* Qw  = (uint32_t*)(Psh + 8 * PSTRIDE);

    int tid = threadIdx.x, warp = tid >> 5, lane = tid & 31;
    const __half* base = qkv + (size_t)b * NTOK * (3 * C) + h * HD;

    for (int idx = tid; idx < NTOK * 32; idx += 256) {
        int m = idx >> 5, w = idx & 31;
        const __half* row = base + (size_t)m * (3 * C);
        __half2 kh = *(const __half2*)(row + C + 2 * w);
        Kw[m * KPITCH + w] = *(uint32_t*)&kh;
        const __half* vr = row + 2 * C;
        __half2 vh = __halves2half2(vr[w], vr[w + 32]);
        Vp[m * KPITCH + w] = *(uint32_t*)&vh;
    }
    __syncthreads();

    float* myP = Psh + warp * PSTRIDE;
    uint32_t* myQ = Qw + warp * 32;

    for (int n = warp; n < NTOK; n += 8) {
        const __half* qrow = base + (size_t)n * (3 * C);
        __half2 qh = *(const __half2*)(qrow + 2 * lane);
        myQ[lane] = *(uint32_t*)&qh;
        __syncwarp();

        float lmax = -1e30f;
        for (int m = lane; m < NTOK; m += 32) {
            const uint32_t* kr = &Kw[m * KPITCH];
            float s0 = 0.f, s1 = 0.f;
            #pragma unroll
            for (int w = 0; w < 32; w += 2) {
                float2 q0 = __half22float2(u32_as_h2(myQ[w]));
                float2 k0 = __half22float2(u32_as_h2(kr[w]));
                float2 q1 = __half22float2(u32_as_h2(myQ[w + 1]));
                float2 k1 = __half22float2(u32_as_h2(kr[w + 1]));
                s0 += q0.x * k0.x + q0.y * k0.y;
                s1 += q1.x * k1.x + q1.y * k1.y;
            }
            float s = (s0 + s1) * 0.125f;
            myP[m] = s;
            lmax = fmaxf(lmax, s);
        }
        #pragma unroll
        for (int o = 16; o; o >>= 1)
            lmax = fmaxf(lmax, __shfl_xor_sync(0xffffffffu, lmax, o));

        float lsum = 0.f;
        for (int m = lane; m < NTOK; m += 32) {
            float p = expf(myP[m] - lmax);
            myP[m] = p;
            lsum += p;
        }
        #pragma unroll
        for (int o = 16; o; o >>= 1)
            lsum += __shfl_xor_sync(0xffffffffu, lsum, o);
        __syncwarp();

        float a0[4] = {0.f, 0.f, 0.f, 0.f};
        float a1[4] = {0.f, 0.f, 0.f, 0.f};
        int m = 0;
        for (; m + 4 <= NTOK; m += 4) {
            #pragma unroll
            for (int u = 0; u < 4; u++) {
                float p = myP[m + u];
                float2 vf = __half22float2(u32_as_h2(Vp[(m + u) * KPITCH + lane]));
                a0[u] += p * vf.x;
                a1[u] += p * vf.y;
            }
        }
        for (; m < NTOK; m++) {
            float p = myP[m];
            float2 vf = __half22float2(u32_as_h2(Vp[m * KPITCH + lane]));
            a0[0] += p * vf.x;
            a1[0] += p * vf.y;
        }
        float inv = 1.0f / lsum;
        float o0 = (a0[0] + a0[1] + a0[2] + a0[3]) * inv;
        float o1 = (a1[0] + a1[1] + a1[2] + a1[3]) * inv;

        __half* orow = out + ((size_t)b * NTOK + n) * C + h * HD;
        orow[lane]      = __float2half_rn(o0);
        orow[lane + 32] = __float2half_rn(o1);
        __syncwarp();
    }
}

// ---------------------------------------------------------------------------
// Launch
// ---------------------------------------------------------------------------
static inline void* symv(const void* symbol) {
    void* p = nullptr;
    cudaGetSymbolAddress(&p, symbol);
    return p;
}

static GemmTask mk_task(const __half* A, int lda, const __half* B, int ldb,
                        void* Cc, int ldc, int out_half,
                        const float* Cin, int ldcin,
                        const float* bias, const float* resid, int ldr,
                        int M, int K, int N,
                        const float* alpha_ptr, int aidx, int do_gelu,
                        __half* gback)
{
    GemmTask t;
    t.A = A; t.lda = lda; t.B = B; t.ldb = ldb;
    t.Cc = Cc; t.ldc = ldc; t.out_half = out_half;
    t.Cin = Cin; t.ldcin = ldcin; t.bias = bias;
    t.resid = resid; t.ldr = ldr;
    t.M = M; t.K = K;
    t.alpha_ptr = alpha_ptr; t.aidx = aidx; t.do_gelu = do_gelu;
    t.gback = gback;
    t.bnCnt = N / 128; t.ctaStart = 0;
    return t;
}

static void launch_batch(GemmTask* tasks, int n)
{
    GemmBatch nb;
    int total = 0;
    for (int i = 0; i < n; i++) {
        tasks[i].ctaStart = total;
        total += tasks[i].bnCnt * ((tasks[i].M + 127) / 128);
        nb.t[i] = tasks[i];
    }
    nb.n = n;
    for (int i = n; i < 4; i++) nb.t[i] = tasks[n - 1];
    hgemm_multi<<<total, 256, GEMM_SMEM>>>(nb);
}

extern "C" void kernel_launch(void* const* d_in, const int* in_sizes, int n_in,
                              void* d_out, int out_size)
{
    const float* x      = (const float*)d_in[0];
    const float* gw     = (const float*)d_in[1];
    const float* n1l_g  = (const float*)d_in[2];
    const float* n1l_b  = (const float*)d_in[3];
    const float* n1s_g  = (const float*)d_in[4];
    const float* n1s_b  = (const float*)d_in[5];
    const float* w_qkv  = (const float*)d_in[6];
    const float* w_proj = (const float*)d_in[7];
    const float* b_proj = (const float*)d_in[8];
    const float* n2l_g  = (const float*)d_in[9];
    const float* n2l_b  = (const float*)d_in[10];
    const float* n2s_g  = (const float*)d_in[11];
    const float* n2s_b  = (const float*)d_in[12];
    const float* w_fc1  = (const float*)d_in[13];
    const float* b_fc1  = (const float*)d_in[14];
    const float* w_fc2  = (const float*)d_in[15];
    const float* b_fc2  = (const float*)d_in[16];
    float* out = (float*)d_out;

    __half* normed = (__half*)symv(g_normed_h);
    __half* qkv    = (__half*)symv(g_qkv_h);
    __half* attn   = (__half*)symv(g_attn_h);
    float*  x1     = (float*)symv(g_x1);
    float*  beff   = (float*)symv(g_beff);
    __half* hL     = (__half*)symv(g_hL_h);
    float*  pre2   = (float*)symv(g_pre2);
    float*  pre3   = (float*)symv(g_pre3);
    __half* h1h    = (__half*)symv(g_h1h);
    __half* h2h    = (__half*)symv(g_h2h);
    __half* h3h    = (__half*)symv(g_h3h);
    float*  P2     = (float*)symv(g_P2);
    float*  P3     = (float*)symv(g_P3);
    __half* wqkvT  = (__half*)symv(g_wqkvT);
    __half* wprojT = (__half*)symv(g_wprojT);
    __half* weffT  = (__half*)symv(g_weffT);
    __half* wfc1T  = (__half*)symv(g_wfc1T);
    __half* wfc2T  = (__half*)symv(g_wfc2T);

    const int attn_smem = (2 * NTOK * KPITCH + 8 * PSTRIDE + 8 * 32) * 4;
    cudaFuncSetAttribute(attn_kernel, cudaFuncAttributeMaxDynamicSharedMemorySize,
                         attn_smem);
    cudaFuncSetAttribute(hgemm_multi, cudaFuncAttributeMaxDynamicSharedMemorySize,
                         GEMM_SMEM);

    // 0. fused weight prep (5 transposes + beff, one launch)
    prep_kernel<<<7489, dim3(32, 8)>>>(w_qkv, w_proj, w_fc1, w_fc2, b_proj, gw);

    // 1. LN1
    ln_kernel<<<T, 256>>>(x, n1l_g, n1l_b, n1s_g, n1s_b, normed);

    // 2. QKV
    {
        GemmTask t[1] = { mk_task(normed, C, wqkvT, C, qkv, 3 * C, 1,
                                  nullptr, 0, nullptr, nullptr, 0,
                                  T, C, 3 * C, nullptr, 0, 0, nullptr) };
        launch_batch(t, 1);
    }

    // 3. Attention
    attn_kernel<<<BATCH * NH, 256, attn_smem>>>(qkv, attn);

    // 4. Projection + residual (large + small concurrently)
    {
        GemmTask t[2] = {
            mk_task(attn, C, wprojT, C, x1, C, 0,
                    nullptr, 0, b_proj, x, C, TH, C, C, nullptr, 0, 0, nullptr),
            mk_task(attn + (size_t)TH * C, C, weffT, C,
                    x1 + (size_t)TH * C, C, 0,
                    nullptr, 0, beff, x + (size_t)TH * C, C, TH, C, C,
                    nullptr, 0, 0, nullptr) };
        launch_batch(t, 2);
    }

    // 5. LN2
    ln_kernel<<<T, 256>>>(x1, n2l_g, n2l_b, n2s_g, n2s_b, normed);

    // 6. FC1: large + pre3 concurrently, then dependent chain
    const __half* ns2 = normed + (size_t)TH * C;
    {
        GemmTask t[2] = {
            mk_task(normed, C, wfc1T, C, hL, HID, 1,
                    nullptr, 0, b_fc1, nullptr, 0, TH, C, HID,
                    nullptr, 0, 1, nullptr),
            mk_task(ns2, C, wfc1T, C, pre3, HID, 0,
                    nullptr, 0, b_fc1, nullptr, 0, TH, 256, HID,
                    nullptr, 0, 0, nullptr) };
        launch_batch(t, 2);
    }
    {
        GemmTask t[1] = { mk_task(ns2 + 256, C, wfc1T + 256, C, pre2, HID, 0,
                                  pre3, HID, nullptr, nullptr, 0, TH, 128, HID,
                                  nullptr, 0, 0, h3h) };
        launch_batch(t, 1);
    }
    {
        GemmTask t[1] = { mk_task(ns2 + 384, C, wfc1T + 384, C, h1h, HID, 1,
                                  pre2, HID, nullptr, nullptr, 0, TH, 384, HID,
                                  nullptr, 0, 1, h2h) };
        launch_batch(t, 1);
    }

    // 7. FC2: all four tasks concurrent; smalls 2/3 go to partial buffers
    float* outS = out + (size_t)TH * C;
    const float* x1S = x1 + (size_t)TH * C;
    {
        GemmTask t[4] = {
            mk_task(hL, HID, wfc2T, HID, out, C, 0,
                    nullptr, 0, b_fc2, x1, C, TH, HID, C, nullptr, 0, 0, nullptr),
            mk_task(h1h, HID, wfc2T, HID, outS, C, 0,
                    nullptr, 0, b_fc2, x1S, C, TH, HID, C, gw, 0, 0, nullptr),
            mk_task(h2h, HID, wfc2T, HID, P2, 384, 0,
                    nullptr, 0, b_fc2, nullptr, 0, TH, HID, 384, gw, 1, 0, nullptr),
            mk_task(h3h, HID, wfc2T, HID, P3, 256, 0,
                    nullptr, 0, b_fc2, nullptr, 0, TH, HID, 256, gw, 2, 0, nullptr) };
        launch_batch(t, 4);
    }
    merge_kernel<<<(TH * 96 + 255) / 256, 256>>>(outS, P2, P3);
}

// round 17
// speedup vs baseline: 1.5723x; 1.0407x over previous
#include <cuda_runtime.h>
#include <cuda_fp16.h>
#include <math.h>
#include <stdint.h>

// ---------------------------------------------------------------------------
// Problem constants
// ---------------------------------------------------------------------------
#define BATCH   64
#define B2      32
#define NTOK    257
#define C       768
#define HID     3072
#define NH      12
#define HD      64
#define T       (BATCH * NTOK)      // 16448 tokens total
#define TH      (B2 * NTOK)         // 8224 tokens per half

// ---------------------------------------------------------------------------
// Scratch (static device allocations; no cudaMalloc allowed)
// ---------------------------------------------------------------------------
__device__ __half g_normed_h[T * C];
__device__ __half g_qkv_h[T * 3 * C];
__device__ __half g_attn_h[T * C];
__device__ float  g_x1[T * C];
__device__ float  g_beff[C];
__device__ __half g_hL_h[TH * HID];
__device__ float  g_pre2[TH * HID];
__device__ float  g_pre3[TH * HID];
__device__ __half g_h1h[TH * HID];
__device__ __half g_h2h[TH * HID];
__device__ __half g_h3h[TH * HID];
__device__ float  g_P2[TH * 384];      // FC2 small partials (alpha folded)
__device__ float  g_P3[TH * 256];
// transposed fp16 weights: WT[n][k], k contiguous
__device__ __half g_wqkvT[3 * C * C];
__device__ __half g_wprojT[C * C];
__device__ __half g_weffT[C * C];
__device__ __half g_wfc1T[HID * C];
__device__ __half g_wfc2T[C * HID];

// ---------------------------------------------------------------------------
// Helpers
// ---------------------------------------------------------------------------
__device__ __forceinline__ float gelu_exact(float v) {
    return 0.5f * v * (1.0f + erff(v * 0.70710678118654752f));
}
__device__ __forceinline__ uint32_t smem_u32(const void* p) {
    uint32_t a;
    asm("{ .reg .u64 t; cvta.to.shared.u64 t, %1; cvt.u32.u64 %0, t; }"
        : "=r"(a) : "l"(p));
    return a;
}
__device__ __forceinline__ void cp_async16(uint32_t dst, const void* src, int srcbytes) {
    asm volatile("cp.async.cg.shared.global [%0], [%1], 16, %2;"
                 :: "r"(dst), "l"(src), "r"(srcbytes));
}
#define CP_COMMIT() asm volatile("cp.async.commit_group;" ::: "memory")
#define CP_WAIT1()  asm volatile("cp.async.wait_group 1;" ::: "memory")

__device__ __forceinline__ void mma_f16(float* c, const uint32_t* a, const uint32_t* b) {
    asm volatile(
        "mma.sync.aligned.m16n8k16.row.col.f32.f16.f16.f32 "
        "{%0,%1,%2,%3}, {%4,%5,%6,%7}, {%8,%9}, {%0,%1,%2,%3};"
        : "+f"(c[0]), "+f"(c[1]), "+f"(c[2]), "+f"(c[3])
        : "r"(a[0]), "r"(a[1]), "r"(a[2]), "r"(a[3]), "r"(b[0]), "r"(b[1]));
}
__device__ __forceinline__ void ldsm_x4(uint32_t* r, uint32_t addr) {
    asm volatile("ldmatrix.sync.aligned.m8n8.x4.shared.b16 {%0,%1,%2,%3}, [%4];"
        : "=r"(r[0]), "=r"(r[1]), "=r"(r[2]), "=r"(r[3]) : "r"(addr));
}
__device__ __forceinline__ void ldsm_x2(uint32_t* r, uint32_t addr) {
    asm volatile("ldmatrix.sync.aligned.m8n8.x2.shared.b16 {%0,%1}, [%2];"
        : "=r"(r[0]), "=r"(r[1]) : "r"(addr));
}
__device__ __forceinline__ __half2 u32_as_h2(uint32_t w) {
    return *reinterpret_cast<__half2*>(&w);
}

extern __shared__ char dsmem[];

// GEMM smem: A/B tiles 128 rows x 64 halves, pitch 72 halves (144B), 3 stages
#define ROWB     144                     // bytes per smem row
#define A_BYTES  (128 * ROWB)            // 18432
#define STG_B    (2 * A_BYTES)           // 36864
#define STAGES   3
#define GEMM_SMEM (STAGES * STG_B)       // 110592 (x2 CTAs = 216KB <= 228KB)

// ---------------------------------------------------------------------------
// Multi-task fp16 GEMM: flattened grid; each CTA resolves its task from the
// batch table (by-value kernel arg), then computes a 128x128 tile.
// BK=64 chunks; pipeline keeps the R14-proven structure (wait -> sync ->
// issue+commit -> compute, sync EVERY chunk), prologue 2, wait_group 1:
// 2 chunks (64KB) in flight during each ~2x longer compute phase.
// K must be a multiple of 64 (nch >= 2) at every call site; M guarded.
// ---------------------------------------------------------------------------
struct GemmTask {
    const __half* A; const __half* B;
    void* Cc; const float* Cin;
    const float* bias; const float* resid;
    const float* alpha_ptr; __half* gback;
    int lda, ldb, ldc, out_half, ldcin, ldr;
    int M, K, aidx, do_gelu, bnCnt, ctaStart;
};
struct GemmBatch { GemmTask t[4]; int n; };

__global__ void __launch_bounds__(256, 2) hgemm_multi(GemmBatch nb)
{
    const int bid = blockIdx.x;
    int ti = 0;
    #pragma unroll
    for (int j = 1; j < 4; j++)
        if (j < nb.n && bid >= nb.t[j].ctaStart) ti = j;
    const GemmTask& tk = nb.t[ti];
    const int local = bid - tk.ctaStart;
    const int bn = local % tk.bnCnt;
    const int bm = local / tk.bnCnt;

    const int tid = threadIdx.x;
    const int wid = tid >> 5, lid = tid & 31;
    const int warpM = wid >> 2;          // 0..1  (64 rows)
    const int warpN = wid & 3;           // 0..3  (32 cols)
    const int lq = lid >> 2;             // 0..7
    const int lr = lid & 3;              // 0..3

    const uint32_t sbase = smem_u32(dsmem);
    const int ldRow = tid >> 3;          // 0..31 (+32*u)
    const int ldQ   = tid & 7;           // 16B quad within 128B of row data

    // ldmatrix lane address components
    const int aRowSel = (lid & 7) + ((lid >> 3) & 1) * 8;
    const int aKb16   = ((lid >> 4) & 1) * 16;
    const int bRowSel = lid & 7;
    const int bKb16   = ((lid >> 3) & 1) * 16;

    float acc[4][4][4];
    #pragma unroll
    for (int mi = 0; mi < 4; mi++)
        #pragma unroll
        for (int ni = 0; ni < 4; ni++)
            #pragma unroll
            for (int j = 0; j < 4; j++) acc[mi][ni][j] = 0.f;

    const __half* A = tk.A; const __half* B = tk.B;
    const int lda = tk.lda, ldb = tk.ldb, M = tk.M;
    const int nch = tk.K >> 6;           // BK = 64

    auto issue = [&](int ci, int st) {
        int k0 = ci << 6;
        uint32_t aB = sbase + (uint32_t)st * STG_B;
        uint32_t bB = aB + A_BYTES;
        #pragma unroll
        for (int u = 0; u < 4; u++) {
            int row = ldRow + u * 32;
            int r = bm * 128 + row;
            bool ok = (r < M);
            const __half* src = A + (size_t)(ok ? r : 0) * lda + k0 + ldQ * 8;
            cp_async16(aB + (uint32_t)(row * ROWB + ldQ * 16), src, ok ? 16 : 0);
        }
        #pragma unroll
        for (int u = 0; u < 4; u++) {
            int row = ldRow + u * 32;
            const __half* src = B + (size_t)(bn * 128 + row) * ldb + k0 + ldQ * 8;
            cp_async16(bB + (uint32_t)(row * ROWB + ldQ * 16), src, 16);
        }
    };

    // prologue: 2 chunks (nch >= 2 at every call site)
    #pragma unroll
    for (int s = 0; s < STAGES - 1; s++) {
        if (s < nch) issue(s, s);
        CP_COMMIT();
    }

    for (int i = 0; i < nch; i++) {
        CP_WAIT1();                       // chunk i resident
        __syncthreads();
        int nx = i + STAGES - 1;
        if (nx < nch) issue(nx, nx % STAGES);
        CP_COMMIT();

        int st = i % STAGES;
        uint32_t aStage = sbase + (uint32_t)st * STG_B;
        uint32_t bStage = aStage + A_BYTES;

        #pragma unroll
        for (int ks = 0; ks < 4; ks++) {
            uint32_t afr[4][4], bfr[4][2];
            #pragma unroll
            for (int mi = 0; mi < 4; mi++) {
                int row = warpM * 64 + mi * 16 + aRowSel;
                ldsm_x4(afr[mi], aStage + (uint32_t)(row * ROWB + ks * 32 + aKb16));
            }
            #pragma unroll
            for (int ni = 0; ni < 4; ni++) {
                int row = warpN * 32 + ni * 8 + bRowSel;
                ldsm_x2(bfr[ni], bStage + (uint32_t)(row * ROWB + ks * 32 + bKb16));
            }
            #pragma unroll
            for (int mi = 0; mi < 4; mi++)
                #pragma unroll
                for (int ni = 0; ni < 4; ni++)
                    mma_f16(acc[mi][ni], afr[mi], bfr[ni]);
        }
    }

    // ---- epilogue ----
    float alpha = tk.alpha_ptr ? tk.alpha_ptr[tk.aidx] : 1.0f;
    #pragma unroll
    for (int mi = 0; mi < 4; mi++) {
        #pragma unroll
        for (int h = 0; h < 2; h++) {
            int r = bm * 128 + warpM * 64 + mi * 16 + lq + h * 8;
            if (r >= M) continue;
            #pragma unroll
            for (int ni = 0; ni < 4; ni++) {
                int cc = bn * 128 + warpN * 32 + ni * 8 + lr * 2;
                float v0 = acc[mi][ni][h * 2 + 0];
                float v1 = acc[mi][ni][h * 2 + 1];
                if (tk.bias) { v0 += tk.bias[cc]; v1 += tk.bias[cc + 1]; }
                v0 *= alpha; v1 *= alpha;
                if (tk.Cin) {
                    const float* cp = tk.Cin + (size_t)r * tk.ldcin + cc;
                    float c0 = cp[0], c1 = cp[1];
                    v0 += c0; v1 += c1;
                    if (tk.gback) {
                        __half2* gp = (__half2*)(tk.gback + (size_t)r * tk.ldcin + cc);
                        *gp = __floats2half2_rn(gelu_exact(c0), gelu_exact(c1));
                    }
                }
                if (tk.resid) {
                    const float* rp = tk.resid + (size_t)r * tk.ldr + cc;
                    v0 += rp[0]; v1 += rp[1];
                }
                if (tk.do_gelu) { v0 = gelu_exact(v0); v1 = gelu_exact(v1); }
                if (tk.out_half) {
                    __half2* op = (__half2*)((__half*)tk.Cc + (size_t)r * tk.ldc + cc);
                    *op = __floats2half2_rn(v0, v1);
                } else {
                    float2* op = (float2*)((float*)tk.Cc + (size_t)r * tk.ldc + cc);
                    *op = make_float2(v0, v1);
                }
            }
        }
    }
}

// ---------------------------------------------------------------------------
// FC2-small merge: outS[:, :384] += P2; outS[:, :256] += P3 (alphas folded)
// ---------------------------------------------------------------------------
__global__ void merge_kernel(float* __restrict__ outS,
                             const float* __restrict__ P2,
                             const float* __restrict__ P3)
{
    int i = blockIdx.x * blockDim.x + threadIdx.x;   // over TH*96 float4s
    if (i >= TH * 96) return;
    int r = i / 96, c4 = i % 96;
    float4 v = *(float4*)(outS + (size_t)r * C + c4 * 4);
    float4 p2 = *(const float4*)(P2 + (size_t)r * 384 + c4 * 4);
    v.x += p2.x; v.y += p2.y; v.z += p2.z; v.w += p2.w;
    if (c4 < 64) {
        float4 p3 = *(const float4*)(P3 + (size_t)r * 256 + c4 * 4);
        v.x += p3.x; v.y += p3.y; v.z += p3.z; v.w += p3.w;
    }
    *(float4*)(outS + (size_t)r * C + c4 * 4) = v;
}

// ---------------------------------------------------------------------------
// LayerNorm: fp32 in, half out
// ---------------------------------------------------------------------------
__global__ __launch_bounds__(256) void ln_kernel(
    const float* __restrict__ x,
    const float* __restrict__ gl, const float* __restrict__ bl,
    const float* __restrict__ gs, const float* __restrict__ bs,
    __half* __restrict__ out)
{
    int row = blockIdx.x;
    const float* xr = x + (size_t)row * C;
    int t = threadIdx.x;
    float v0 = xr[t], v1 = xr[t + 256], v2 = xr[t + 512];
    float s = v0 + v1 + v2;
    float ss = v0 * v0 + v1 * v1 + v2 * v2;
    #pragma unroll
    for (int o = 16; o; o >>= 1) {
        s  += __shfl_xor_sync(0xffffffffu, s, o);
        ss += __shfl_xor_sync(0xffffffffu, ss, o);
    }
    __shared__ float sm[2][8];
    int warp = t >> 5, lane = t & 31;
    if (!lane) { sm[0][warp] = s; sm[1][warp] = ss; }
    __syncthreads();
    if (t < 32) {
        float a = (lane < 8) ? sm[0][lane] : 0.f;
        float b = (lane < 8) ? sm[1][lane] : 0.f;
        #pragma unroll
        for (int o = 4; o; o >>= 1) {
            a += __shfl_xor_sync(0xffffffffu, a, o);
            b += __shfl_xor_sync(0xffffffffu, b, o);
        }
        if (!lane) { sm[0][0] = a; sm[1][0] = b; }
    }
    __syncthreads();
    float mean = sm[0][0] * (1.0f / C);
    float var  = sm[1][0] * (1.0f / C) - mean * mean;
    float rstd = rsqrtf(var + 1e-5f);
    const float* g  = (row < TH) ? gl : gs;
    const float* bb = (row < TH) ? bl : bs;
    __half* orow = out + (size_t)row * C;
    orow[t]       = __float2half_rn((v0 - mean) * rstd * g[t]       + bb[t]);
    orow[t + 256] = __float2half_rn((v1 - mean) * rstd * g[t + 256] + bb[t + 256]);
    orow[t + 512] = __float2half_rn((v2 - mean) * rstd * g[t + 512] + bb[t + 512]);
}

// ---------------------------------------------------------------------------
// Fused weight prep: all 5 transposes (fp32 [K][N] -> half [N][K]) + beff,
// one flattened grid.  Block ranges hardcoded:
//   [0,1728)     w_qkv  -> g_wqkvT   (N=2304, K=768,  nbX=72)
//   [1728,2304)  w_proj -> g_wprojT  (N=768,  K=768,  nbX=24)
//   [2304,2880)  w_proj -> g_weffT   (masked, nbX=24)
//   [2880,5184)  w_fc1  -> g_wfc1T   (N=3072, K=768,  nbX=96)
//   [5184,7488)  w_fc2  -> g_wfc2T   (N=768,  K=3072, nbX=24)
//   7488         beff
// ---------------------------------------------------------------------------
__global__ void prep_kernel(const float* __restrict__ w_qkv,
                            const float* __restrict__ w_proj,
                            const float* __restrict__ w_fc1,
                            const float* __restrict__ w_fc2,
                            const float* __restrict__ b_proj,
                            const float* __restrict__ g)
{
    int bidx = blockIdx.x;
    if (bidx == 7488) {
        int i = threadIdx.y * 32 + threadIdx.x;
        for (; i < C; i += 256) {
            float m = g[0];
            if (i < 384) m += g[1];
            if (i < 256) m += g[2];
            g_beff[i] = b_proj[i] * m;
        }
        return;
    }
    const float* in; __half* outp; int K, N, nbX, mode, rel;
    if (bidx < 1728)      { in = w_qkv;  outp = g_wqkvT;  K = C;   N = 3 * C; nbX = 72; mode = 0; rel = bidx; }
    else if (bidx < 2304) { in = w_proj; outp = g_wprojT; K = C;   N = C;     nbX = 24; mode = 0; rel = bidx - 1728; }
    else if (bidx < 2880) { in = w_proj; outp = g_weffT;  K = C;   N = C;     nbX = 24; mode = 1; rel = bidx - 2304; }
    else if (bidx < 5184) { in = w_fc1;  outp = g_wfc1T;  K = C;   N = HID;   nbX = 96; mode = 0; rel = bidx - 2880; }
    else                  { in = w_fc2;  outp = g_wfc2T;  K = HID; N = C;     nbX = 24; mode = 0; rel = bidx - 5184; }

    __shared__ float tile[32][33];
    int nb = (rel % nbX) * 32, kb = (rel / nbX) * 32;
    int tx = threadIdx.x, ty = threadIdx.y;   // 32 x 8
    #pragma unroll
    for (int j = 0; j < 32; j += 8)
        tile[ty + j][tx] = in[(size_t)(kb + ty + j) * N + nb + tx];
    __syncthreads();
    #pragma unroll
    for (int j = 0; j < 32; j += 8) {
        int n = nb + ty + j, k = kb + tx;
        float v = tile[tx][ty + j];
        if (mode) {
            float m = g[0];
            if (k < 384 && n < 384) m += g[1];
            if (k < 256 && n < 256) m += g[2];
            v *= m;
        }
        outp[(size_t)n * K + k] = __float2half_rn(v);
    }
}

// ---------------------------------------------------------------------------
// Attention: one block per (b, h). Half in/out, fp32 softmax.
// ---------------------------------------------------------------------------
#define KPITCH 33
#define PSTRIDE 258

__global__ __launch_bounds__(256) void attn_kernel(
    const __half* __restrict__ qkv, __half* __restrict__ out)
{
    int bh = blockIdx.x;
    int b = bh / NH, h = bh % NH;
    uint32_t* Kw = (uint32_t*)dsmem;
    uint32_t* Vp = Kw + NTOK * KPITCH;
    float*    Psh = (float*)(Vp + NTOK * KPITCH);
    uint32_t* Qw  = (uint32_t*)(Psh + 8 * PSTRIDE);

    int tid = threadIdx.x, warp = tid >> 5, lane = tid & 31;
    const __half* base = qkv + (size_t)b * NTOK * (3 * C) + h * HD;

    for (int idx = tid; idx < NTOK * 32; idx += 256) {
        int m = idx >> 5, w = idx & 31;
        const __half* row = base + (size_t)m * (3 * C);
        __half2 kh = *(const __half2*)(row + C + 2 * w);
        Kw[m * KPITCH + w] = *(uint32_t*)&kh;
        const __half* vr = row + 2 * C;
        __half2 vh = __halves2half2(vr[w], vr[w + 32]);
        Vp[m * KPITCH + w] = *(uint32_t*)&vh;
    }
    __syncthreads();

    float* myP = Psh + warp * PSTRIDE;
    uint32_t* myQ = Qw + warp * 32;

    for (int n = warp; n < NTOK; n += 8) {
        const __half* qrow = base + (size_t)n * (3 * C);
        __half2 qh = *(const __half2*)(qrow + 2 * lane);
        myQ[lane] = *(uint32_t*)&qh;
        __syncwarp();

        float lmax = -1e30f;
        for (int m = lane; m < NTOK; m += 32) {
            const uint32_t* kr = &Kw[m * KPITCH];
            float s0 = 0.f, s1 = 0.f;
            #pragma unroll
            for (int w = 0; w < 32; w += 2) {
                float2 q0 = __half22float2(u32_as_h2(myQ[w]));
                float2 k0 = __half22float2(u32_as_h2(kr[w]));
                float2 q1 = __half22float2(u32_as_h2(myQ[w + 1]));
                float2 k1 = __half22float2(u32_as_h2(kr[w + 1]));
                s0 += q0.x * k0.x + q0.y * k0.y;
                s1 += q1.x * k1.x + q1.y * k1.y;
            }
            float s = (s0 + s1) * 0.125f;
            myP[m] = s;
            lmax = fmaxf(lmax, s);
        }
        #pragma unroll
        for (int o = 16; o; o >>= 1)
            lmax = fmaxf(lmax, __shfl_xor_sync(0xffffffffu, lmax, o));

        float lsum = 0.f;
        for (int m = lane; m < NTOK; m += 32) {
            float p = expf(myP[m] - lmax);
            myP[m] = p;
            lsum += p;
        }
        #pragma unroll
        for (int o = 16; o; o >>= 1)
            lsum += __shfl_xor_sync(0xffffffffu, lsum, o);
        __syncwarp();

        float a0[4] = {0.f, 0.f, 0.f, 0.f};
        float a1[4] = {0.f, 0.f, 0.f, 0.f};
        int m = 0;
        for (; m + 4 <= NTOK; m += 4) {
            #pragma unroll
            for (int u = 0; u < 4; u++) {
                float p = myP[m + u];
                float2 vf = __half22float2(u32_as_h2(Vp[(m + u) * KPITCH + lane]));
                a0[u] += p * vf.x;
                a1[u] += p * vf.y;
            }
        }
        for (; m < NTOK; m++) {
            float p = myP[m];
            float2 vf = __half22float2(u32_as_h2(Vp[m * KPITCH + lane]));
            a0[0] += p * vf.x;
            a1[0] += p * vf.y;
        }
        float inv = 1.0f / lsum;
        float o0 = (a0[0] + a0[1] + a0[2] + a0[3]) * inv;
        float o1 = (a1[0] + a1[1] + a1[2] + a1[3]) * inv;

        __half* orow = out + ((size_t)b * NTOK + n) * C + h * HD;
        orow[lane]      = __float2half_rn(o0);
        orow[lane + 32] = __float2half_rn(o1);
        __syncwarp();
    }
}

// ---------------------------------------------------------------------------
// Launch
// ---------------------------------------------------------------------------
static inline void* symv(const void* symbol) {
    void* p = nullptr;
    cudaGetSymbolAddress(&p, symbol);
    return p;
}

static GemmTask mk_task(const __half* A, int lda, const __half* B, int ldb,
                        void* Cc, int ldc, int out_half,
                        const float* Cin, int ldcin,
                        const float* bias, const float* resid, int ldr,
                        int M, int K, int N,
                        const float* alpha_ptr, int aidx, int do_gelu,
                        __half* gback)
{
    GemmTask t;
    t.A = A; t.lda = lda; t.B = B; t.ldb = ldb;
    t.Cc = Cc; t.ldc = ldc; t.out_half = out_half;
    t.Cin = Cin; t.ldcin = ldcin; t.bias = bias;
    t.resid = resid; t.ldr = ldr;
    t.M = M; t.K = K;
    t.alpha_ptr = alpha_ptr; t.aidx = aidx; t.do_gelu = do_gelu;
    t.gback = gback;
    t.bnCnt = N / 128; t.ctaStart = 0;
    return t;
}

static void launch_batch(GemmTask* tasks, int n)
{
    GemmBatch nb;
    int total = 0;
    for (int i = 0; i < n; i++) {
        tasks[i].ctaStart = total;
        total += tasks[i].bnCnt * ((tasks[i].M + 127) / 128);
        nb.t[i] = tasks[i];
    }
    nb.n = n;
    for (int i = n; i < 4; i++) nb.t[i] = tasks[n - 1];
    hgemm_multi<<<total, 256, GEMM_SMEM>>>(nb);
}

extern "C" void kernel_launch(void* const* d_in, const int* in_sizes, int n_in,
                              void* d_out, int out_size)
{
    const float* x      = (const float*)d_in[0];
    const float* gw     = (const float*)d_in[1];
    const float* n1l_g  = (const float*)d_in[2];
    const float* n1l_b  = (const float*)d_in[3];
    const float* n1s_g  = (const float*)d_in[4];
    const float* n1s_b  = (const float*)d_in[5];
    const float* w_qkv  = (const float*)d_in[6];
    const float* w_proj = (const float*)d_in[7];
    const float* b_proj = (const float*)d_in[8];
    const float* n2l_g  = (const float*)d_in[9];
    const float* n2l_b  = (const float*)d_in[10];
    const float* n2s_g  = (const float*)d_in[11];
    const float* n2s_b  = (const float*)d_in[12];
    const float* w_fc1  = (const float*)d_in[13];
    const float* b_fc1  = (const float*)d_in[14];
    const float* w_fc2  = (const float*)d_in[15];
    const float* b_fc2  = (const float*)d_in[16];
    float* out = (float*)d_out;

    __half* normed = (__half*)symv(g_normed_h);
    __half* qkv    = (__half*)symv(g_qkv_h);
    __half* attn   = (__half*)symv(g_attn_h);
    float*  x1     = (float*)symv(g_x1);
    float*  beff   = (float*)symv(g_beff);
    __half* hL     = (__half*)symv(g_hL_h);
    float*  pre2   = (float*)symv(g_pre2);
    float*  pre3   = (float*)symv(g_pre3);
    __half* h1h    = (__half*)symv(g_h1h);
    __half* h2h    = (__half*)symv(g_h2h);
    __half* h3h    = (__half*)symv(g_h3h);
    float*  P2     = (float*)symv(g_P2);
    float*  P3     = (float*)symv(g_P3);
    __half* wqkvT  = (__half*)symv(g_wqkvT);
    __half* wprojT = (__half*)symv(g_wprojT);
    __half* weffT  = (__half*)symv(g_weffT);
    __half* wfc1T  = (__half*)symv(g_wfc1T);
    __half* wfc2T  = (__half*)symv(g_wfc2T);

    const int attn_smem = (2 * NTOK * KPITCH + 8 * PSTRIDE + 8 * 32) * 4;
    cudaFuncSetAttribute(attn_kernel, cudaFuncAttributeMaxDynamicSharedMemorySize,
                         attn_smem);
    cudaFuncSetAttribute(hgemm_multi, cudaFuncAttributeMaxDynamicSharedMemorySize,
                         GEMM_SMEM);

    // 0. fused weight prep (5 transposes + beff, one launch)
    prep_kernel<<<7489, dim3(32, 8)>>>(w_qkv, w_proj, w_fc1, w_fc2, b_proj, gw);

    // 1. LN1
    ln_kernel<<<T, 256>>>(x, n1l_g, n1l_b, n1s_g, n1s_b, normed);

    // 2. QKV
    {
        GemmTask t[1] = { mk_task(normed, C, wqkvT, C, qkv, 3 * C, 1,
                                  nullptr, 0, nullptr, nullptr, 0,
                                  T, C, 3 * C, nullptr, 0, 0, nullptr) };
        launch_batch(t, 1);
    }

    // 3. Attention
    attn_kernel<<<BATCH * NH, 256, attn_smem>>>(qkv, attn);

    // 4. Projection + residual (large + small concurrently)
    {
        GemmTask t[2] = {
            mk_task(attn, C, wprojT, C, x1, C, 0,
                    nullptr, 0, b_proj, x, C, TH, C, C, nullptr, 0, 0, nullptr),
            mk_task(attn + (size_t)TH * C, C, weffT, C,
                    x1 + (size_t)TH * C, C, 0,
                    nullptr, 0, beff, x + (size_t)TH * C, C, TH, C, C,
                    nullptr, 0, 0, nullptr) };
        launch_batch(t, 2);
    }

    // 5. LN2
    ln_kernel<<<T, 256>>>(x1, n2l_g, n2l_b, n2s_g, n2s_b, normed);

    // 6. FC1: large + pre3 concurrently, then dependent chain
    const __half* ns2 = normed + (size_t)TH * C;
    {
        GemmTask t[2] = {
            mk_task(normed, C, wfc1T, C, hL, HID, 1,
                    nullptr, 0, b_fc1, nullptr, 0, TH, C, HID,
                    nullptr, 0, 1, nullptr),
            mk_task(ns2, C, wfc1T, C, pre3, HID, 0,
                    nullptr, 0, b_fc1, nullptr, 0, TH, 256, HID,
                    nullptr, 0, 0, nullptr) };
        launch_batch(t, 2);
    }
    {
        GemmTask t[1] = { mk_task(ns2 + 256, C, wfc1T + 256, C, pre2, HID, 0,
                                  pre3, HID, nullptr, nullptr, 0, TH, 128, HID,
                                  nullptr, 0, 0, h3h) };
        launch_batch(t, 1);
    }
    {
        GemmTask t[1] = { mk_task(ns2 + 384, C, wfc1T + 384, C, h1h, HID, 1,
                                  pre2, HID, nullptr, nullptr, 0, TH, 384, HID,
                                  nullptr, 0, 1, h2h) };
        launch_batch(t, 1);
    }

    // 7. FC2: all four tasks concurrent; smalls 2/3 go to partial buffers
    float* outS = out + (size_t)TH * C;
    const float* x1S = x1 + (size_t)TH * C;
    {
        GemmTask t[4] = {
            mk_task(hL, HID, wfc2T, HID, out, C, 0,
                    nullptr, 0, b_fc2, x1, C, TH, HID, C, nullptr, 0, 0, nullptr),
            mk_task(h1h, HID, wfc2T, HID, outS, C, 0,
                    nullptr, 0, b_fc2, x1S, C, TH, HID, C, gw, 0, 0, nullptr),
            mk_task(h2h, HID, wfc2T, HID, P2, 384, 0,
                    nullptr, 0, b_fc2, nullptr, 0, TH, HID, 384, gw, 1, 0, nullptr),
            mk_task(h3h, HID, wfc2T, HID, P3, 256, 0,
                    nullptr, 0, b_fc2, nullptr, 0, TH, HID, 256, gw, 2, 0, nullptr) };
        launch_batch(t, 4);
    }
    merge_kernel<<<(TH * 96 + 255) / 256, 256>>>(outS, P2, P3);
}